// round 6
// baseline (speedup 1.0000x reference)
#include <cuda_runtime.h>
#include <cstdint>
#include <math.h>

#define N 8192
#define D 512
#define BM 128
#define NT (N / BM)                 // 64
#define NPAIRS (NT * (NT + 1) / 2)  // 2080
#define BK 128                      // int8 K elements per chunk (128B rows)
#define NCHUNKS (D / BK)            // 4
#define NSTAGE 3
#define TILE_BYTES (BM * BK)        // 16384 (int8)
#define SMEM_BYTES (1024 + 2 * NSTAGE * TILE_BYTES)

__device__ int8_t g_q[N * D];       // quantized unit rows
__device__ float  g_scale[N];       // per-row quant scale
__device__ double g_accum;

// ---------------------------------------------------------------------------
// PTX helpers (arch-agnostic)
// ---------------------------------------------------------------------------
__device__ __forceinline__ uint32_t smem_u32(const void* p) {
    uint32_t a;
    asm("{ .reg .u64 t; cvta.to.shared.u64 t, %1; cvt.u32.u64 %0, t; }" : "=r"(a) : "l"(p));
    return a;
}

__device__ __forceinline__ void cp16(uint32_t saddr, const void* g) {
    asm volatile("cp.async.cg.shared.global [%0], [%1], 16;" :: "r"(saddr), "l"(g) : "memory");
}
__device__ __forceinline__ void cp_commit() {
    asm volatile("cp.async.commit_group;" ::: "memory");
}
template <int NN>
__device__ __forceinline__ void cp_wait() {
    asm volatile("cp.async.wait_group %0;" :: "n"(NN) : "memory");
}

__device__ __forceinline__ void ldsm_x4(uint32_t* r, uint32_t addr) {
    asm volatile("ldmatrix.sync.aligned.m8n8.x4.shared.b16 {%0,%1,%2,%3}, [%4];"
                 : "=r"(r[0]), "=r"(r[1]), "=r"(r[2]), "=r"(r[3]) : "r"(addr));
}

// int8 IMMA, k=32 per instruction, exact s32 accumulate.
__device__ __forceinline__ void imma16832(int* d, const uint32_t* a,
                                          uint32_t b0, uint32_t b1) {
    asm volatile(
        "mma.sync.aligned.m16n8k32.row.col.s32.s8.s8.s32 "
        "{%0,%1,%2,%3}, {%4,%5,%6,%7}, {%8,%9}, {%0,%1,%2,%3};"
        : "+r"(d[0]), "+r"(d[1]), "+r"(d[2]), "+r"(d[3])
        : "r"(a[0]), "r"(a[1]), "r"(a[2]), "r"(a[3]), "r"(b0), "r"(b1));
}

// ---------------------------------------------------------------------------
// Kernel 1: row L2-normalize + per-row int8 quantization. One WARP per row.
// ---------------------------------------------------------------------------
__global__ __launch_bounds__(256) void quantize_kernel(const float* __restrict__ in) {
    int row  = blockIdx.x * 8 + (threadIdx.x >> 5);
    int lane = threadIdx.x & 31;
    if (blockIdx.x == 0 && threadIdx.x == 0) g_accum = 0.0;

    const float4* src = (const float4*)(in + (size_t)row * D);
    float4 v[4];
    float ss = 0.0f;
    #pragma unroll
    for (int i = 0; i < 4; i++) {
        v[i] = src[i * 32 + lane];
        ss += v[i].x * v[i].x + v[i].y * v[i].y + v[i].z * v[i].z + v[i].w * v[i].w;
    }
    #pragma unroll
    for (int o = 16; o; o >>= 1) ss += __shfl_xor_sync(0xffffffffu, ss, o);
    float inv = rsqrtf(ss);

    // per-row max of |y|
    float amax = 0.0f;
    #pragma unroll
    for (int i = 0; i < 4; i++) {
        amax = fmaxf(amax, fmaxf(fmaxf(fabsf(v[i].x), fabsf(v[i].y)),
                                 fmaxf(fabsf(v[i].z), fabsf(v[i].w))));
    }
    amax *= inv;
    #pragma unroll
    for (int o = 16; o; o >>= 1) amax = fmaxf(amax, __shfl_xor_sync(0xffffffffu, amax, o));

    float s    = amax * (1.0f / 127.0f);
    float qmul = inv * (127.0f / amax);     // y -> q
    if (lane == 0) g_scale[row] = s;

    uint32_t* dst = (uint32_t*)(g_q + (size_t)row * D);
    #pragma unroll
    for (int i = 0; i < 4; i++) {
        int q0 = __float2int_rn(v[i].x * qmul);
        int q1 = __float2int_rn(v[i].y * qmul);
        int q2 = __float2int_rn(v[i].z * qmul);
        int q3 = __float2int_rn(v[i].w * qmul);
        uint32_t w = (uint32_t)(q0 & 0xff) | ((uint32_t)(q1 & 0xff) << 8) |
                     ((uint32_t)(q2 & 0xff) << 16) | ((uint32_t)(q3 & 0xff) << 24);
        dst[i * 32 + lane] = w;
    }
}

// ---------------------------------------------------------------------------
// Kernel 2: upper-triangle 128x128 Gram tiles via IMMA s8 (k32).
// 256 threads = 8 warps (2 x 4), warp tile 64x32.
// 3-stage cp.async pipeline, one __syncthreads per 128-deep K-chunk.
// SMEM tiles [128 rows][128 int8], 128B rows, XOR-swizzled 16B chunks.
// ---------------------------------------------------------------------------
extern __shared__ char dynsmem[];

__global__ __launch_bounds__(256, 2) void gram_imma_kernel() {
    int b = blockIdx.x;
    int bj = (int)((sqrtf(8.0f * (float)b + 1.0f) - 1.0f) * 0.5f);
    while ((bj + 1) * (bj + 2) / 2 <= b) bj++;
    while (bj * (bj + 1) / 2 > b) bj--;
    int bi = b - bj * (bj + 1) / 2;

    const int8_t* __restrict__ gA = g_q + (size_t)bi * BM * D;
    const int8_t* __restrict__ gB = g_q + (size_t)bj * BM * D;
    const bool diag = (bi == bj);

    int t      = threadIdx.x;
    int wid    = t >> 5;
    int lane   = t & 31;
    int warp_m = wid & 1;    // 2 warps over M (64 each)
    int warp_n = wid >> 1;   // 4 warps over N (32 each)

    __shared__ float sScale[256];   // [0..127]=A-row scales, [128..255]=B-row scales
    if (t < 128) sScale[t] = g_scale[bi * BM + t];
    else         sScale[t] = g_scale[bj * BM + (t - 128)];

    uint32_t smem0 = smem_u32(dynsmem);
    uint32_t base  = (smem0 + 1023) & ~1023u;
    uint32_t sA[NSTAGE], sB[NSTAGE];
    #pragma unroll
    for (int s = 0; s < NSTAGE; s++) {
        sA[s] = base + (2 * s)     * TILE_BYTES;
        sB[s] = base + (2 * s + 1) * TILE_BYTES;
    }

    // --- async tile loader: 128 rows x 128 int8 (= 8 x 16B chunks/row) ---
    auto load_tile = [&](const int8_t* __restrict__ g, uint32_t s, int k0) {
        int row = t >> 1;
        const char* gp = (const char*)(g + (size_t)row * D + k0);
        uint32_t srow = s + (uint32_t)row * 128;
        #pragma unroll
        for (int i = 0; i < 4; i++) {
            int c = (t & 1) * 4 + i;
            cp16(srow + (((uint32_t)c ^ (row & 7)) << 4), gp + c * 16);
        }
    };

    int acc[4][4][4];
    #pragma unroll
    for (int mi = 0; mi < 4; mi++)
        #pragma unroll
        for (int nj = 0; nj < 4; nj++)
            #pragma unroll
            for (int r = 0; r < 4; r++) acc[mi][nj][r] = 0;

    // prologue: stages 0 and 1 in flight
    load_tile(gA, sA[0], 0);
    load_tile(gB, sB[0], 0);
    cp_commit();
    load_tile(gA, sA[1], BK);
    load_tile(gB, sB[1], BK);
    cp_commit();

    // ldmatrix lane addressing (b16 view: 64 b16 per row; k32 step = 2 x 16B chunks)
    int a_row = warp_m * 64 + (lane & 15);                            // + mi*16
    int a_kh  = lane >> 4;                                            // 16B half select
    int b_row = warp_n * 32 + (lane & 7) + (((lane >> 3) & 1) << 3);  // + p*16

    for (int c = 0; c < NCHUNKS; c++) {
        if (c < NCHUNKS - 1) cp_wait<1>(); else cp_wait<0>();
        __syncthreads();

        if (c + 2 < NCHUNKS) {
            load_tile(gA, sA[(c + 2) % NSTAGE], (c + 2) * BK);
            load_tile(gB, sB[(c + 2) % NSTAGE], (c + 2) * BK);
            cp_commit();
        }

        uint32_t a_base = sA[c % NSTAGE], b_base = sB[c % NSTAGE];
        #pragma unroll
        for (int kk = 0; kk < 4; kk++) {          // 4 k32-steps per 128-chunk
            uint32_t Af[4][4], Bf[2][4];
            int kchunk = kk * 2 + a_kh;           // 16B-chunk index in row (0..7)
            #pragma unroll
            for (int mi = 0; mi < 4; mi++) {
                int r = a_row + mi * 16;
                ldsm_x4(Af[mi], a_base + (uint32_t)r * 128 +
                                (((uint32_t)kchunk ^ (r & 7)) << 4));
            }
            #pragma unroll
            for (int p = 0; p < 2; p++) {
                int r = b_row + p * 16;
                ldsm_x4(Bf[p], b_base + (uint32_t)r * 128 +
                               (((uint32_t)kchunk ^ (r & 7)) << 4));
            }
            #pragma unroll
            for (int mi = 0; mi < 4; mi++)
                #pragma unroll
                for (int nj = 0; nj < 4; nj++)
                    imma16832(acc[mi][nj], Af[mi],
                              Bf[nj >> 1][nj & 1], Bf[nj >> 1][(nj & 1) + 2]);
        }
    }

    // Epilogue: scale (s_i * s_j), relu, strict-upper mask on diagonal tiles.
    int lrow0 = warp_m * 64 + (lane >> 2);
    int lcol0 = warp_n * 32 + (lane & 3) * 2;

    float si[4][2], sj[4][2];
    #pragma unroll
    for (int mi = 0; mi < 4; mi++)
        #pragma unroll
        for (int h = 0; h < 2; h++)
            si[mi][h] = sScale[lrow0 + mi * 16 + h * 8];
    #pragma unroll
    for (int nj = 0; nj < 4; nj++)
        #pragma unroll
        for (int bcol = 0; bcol < 2; bcol++)
            sj[nj][bcol] = sScale[128 + lcol0 + nj * 8 + bcol];

    float local = 0.0f;
    #pragma unroll
    for (int mi = 0; mi < 4; mi++) {
        #pragma unroll
        for (int nj = 0; nj < 4; nj++) {
            #pragma unroll
            for (int r = 0; r < 4; r++) {
                int h  = r >> 1;
                int bc = r & 1;
                int im = lrow0 + mi * 16 + h * 8;
                int jn = lcol0 + nj * 8 + bc;
                int d  = acc[mi][nj][r];
                bool ok = diag ? (im < jn) : true;
                if (ok && d > 0) local += (float)d * si[mi][h] * sj[nj][bc];
            }
        }
    }

    #pragma unroll
    for (int o = 16; o; o >>= 1) local += __shfl_xor_sync(0xffffffffu, local, o);
    __shared__ float red[8];
    if (lane == 0) red[wid] = local;
    __syncthreads();
    if (t == 0) {
        float s = 0.0f;
        #pragma unroll
        for (int w = 0; w < 8; w++) s += red[w];
        atomicAdd(&g_accum, (double)s);
    }
}

// ---------------------------------------------------------------------------
// Kernel 3: finalize. Off-diagonal symmetric sum doubled, mean over N*N.
// ---------------------------------------------------------------------------
__global__ void finalize_kernel(float* __restrict__ out, int out_size) {
    double v = 2.0 * g_accum / ((double)N * (double)N);
    float f = (float)v;
    out[0] = f;
    if (out_size > 1) out[1] = f;
}

extern "C" void kernel_launch(void* const* d_in, const int* in_sizes, int n_in,
                              void* d_out, int out_size) {
    const float* id = (const float*)d_in[0];
    cudaFuncSetAttribute(gram_imma_kernel, cudaFuncAttributeMaxDynamicSharedMemorySize,
                         SMEM_BYTES);
    quantize_kernel<<<N / 8, 256>>>(id);
    gram_imma_kernel<<<NPAIRS, 256, SMEM_BYTES>>>();
    finalize_kernel<<<1, 1>>>((float*)d_out, out_size);
}

// round 7
// speedup vs baseline: 1.4145x; 1.4145x over previous
#include <cuda_runtime.h>
#include <cuda_fp16.h>
#include <cstdint>
#include <math.h>

#define N 8192
#define D 512
#define BM 128
#define NT (N / BM)                 // 64
#define NPAIRS (NT * (NT + 1) / 2)  // 2080
#define BK 64                       // K elements per chunk
#define NCHUNKS (D / BK)            // 8
#define NSTAGE 3
#define TILE_BYTES (BM * BK * 2)    // 16384 (fp16)
#define SMEM_BYTES (1024 + 2 * NSTAGE * TILE_BYTES)   // 99328; F path fits inside
#define GRID_SMS 148
#define FSTRIDE 132                 // half2 row stride for F-path smem

__device__ __half  g_nrm[N * D];
__device__ double  g_accum;
__device__ unsigned g_ctr;          // bits 0-15: lo pops, bits 16-31: hi pops

// ---------------------------------------------------------------------------
// PTX helpers (arch-agnostic, sm_80-era)
// ---------------------------------------------------------------------------
__device__ __forceinline__ uint32_t smem_u32(const void* p) {
    uint32_t a;
    asm("{ .reg .u64 t; cvta.to.shared.u64 t, %1; cvt.u32.u64 %0, t; }" : "=r"(a) : "l"(p));
    return a;
}
__device__ __forceinline__ void cp16(uint32_t saddr, const void* g) {
    asm volatile("cp.async.cg.shared.global [%0], [%1], 16;" :: "r"(saddr), "l"(g) : "memory");
}
__device__ __forceinline__ void cp_commit() {
    asm volatile("cp.async.commit_group;" ::: "memory");
}
template <int NN>
__device__ __forceinline__ void cp_wait() {
    asm volatile("cp.async.wait_group %0;" :: "n"(NN) : "memory");
}
__device__ __forceinline__ void ldsm_x4(uint32_t* r, uint32_t addr) {
    asm volatile("ldmatrix.sync.aligned.m8n8.x4.shared.b16 {%0,%1,%2,%3}, [%4];"
                 : "=r"(r[0]), "=r"(r[1]), "=r"(r[2]), "=r"(r[3]) : "r"(addr));
}
__device__ __forceinline__ void mma16816_f16(uint32_t* d, const uint32_t* a,
                                             uint32_t b0, uint32_t b1) {
    asm volatile(
        "mma.sync.aligned.m16n8k16.row.col.f16.f16.f16.f16 "
        "{%0,%1}, {%2,%3,%4,%5}, {%6,%7}, {%0,%1};"
        : "+r"(d[0]), "+r"(d[1])
        : "r"(a[0]), "r"(a[1]), "r"(a[2]), "r"(a[3]), "r"(b0), "r"(b1));
}

__device__ __forceinline__ void decode_tile(int b, int& bi, int& bj) {
    int j = (int)((sqrtf(8.0f * (float)b + 1.0f) - 1.0f) * 0.5f);
    while ((j + 1) * (j + 2) / 2 <= b) j++;
    while (j * (j + 1) / 2 > b) j--;
    bi = b - j * (j + 1) / 2;
    bj = j;
}

// ---------------------------------------------------------------------------
// Kernel 1: row L2-normalize fp32 -> fp16. One WARP per row. Resets globals.
// ---------------------------------------------------------------------------
__global__ __launch_bounds__(256) void normalize_kernel(const float* __restrict__ in) {
    int row  = blockIdx.x * 8 + (threadIdx.x >> 5);
    int lane = threadIdx.x & 31;
    if (blockIdx.x == 0 && threadIdx.x == 0) { g_accum = 0.0; g_ctr = 0u; }

    const float4* src = (const float4*)(in + (size_t)row * D);
    float4 v[4];
    float ss = 0.0f;
    #pragma unroll
    for (int i = 0; i < 4; i++) {
        v[i] = src[i * 32 + lane];
        ss += v[i].x * v[i].x + v[i].y * v[i].y + v[i].z * v[i].z + v[i].w * v[i].w;
    }
    #pragma unroll
    for (int o = 16; o; o >>= 1) ss += __shfl_xor_sync(0xffffffffu, ss, o);
    float inv = rsqrtf(ss);

    uint2* dst = (uint2*)(g_nrm + (size_t)row * D);
    #pragma unroll
    for (int i = 0; i < 4; i++) {
        __half2 lo = __floats2half2_rn(v[i].x * inv, v[i].y * inv);
        __half2 hi = __floats2half2_rn(v[i].z * inv, v[i].w * inv);
        uint2 o2;
        o2.x = *(uint32_t*)&lo;
        o2.y = *(uint32_t*)&hi;
        dst[i * 32 + lane] = o2;
    }
}

// ---------------------------------------------------------------------------
// Kernel 2: persistent dual-pipe gram. 296 CTAs (2/SM):
//   bid < 148  -> HMMA path (tensor pipe), pops tiles from LOW end
//   bid >= 148 -> HFMA2 path (fma pipe),   pops tiles from HIGH end
// ---------------------------------------------------------------------------
extern __shared__ char dynsmem[];

__global__ __launch_bounds__(256, 2) void gram_dual_kernel() {
    const bool isF = (blockIdx.x >= GRID_SMS);
    int t    = threadIdx.x;
    int wid  = t >> 5;
    int lane = t & 31;

    uint32_t smem0 = smem_u32(dynsmem);
    uint32_t base  = (smem0 + 1023) & ~1023u;
    char* basep = dynsmem + (base - smem0);

    __shared__ int   s_tile;
    __shared__ float red[8];

    float local = 0.0f;

    // =========================== HMMA path state ===========================
    int warp_m = wid & 1;
    int warp_n = wid >> 1;
    uint32_t sA[NSTAGE], sB[NSTAGE];
    #pragma unroll
    for (int s = 0; s < NSTAGE; s++) {
        sA[s] = base + (2 * s)     * TILE_BYTES;
        sB[s] = base + (2 * s + 1) * TILE_BYTES;
    }
    int a_row = warp_m * 64 + (lane & 15);
    int a_kq  = (lane >> 4) * 8;
    int b_row = warp_n * 32 + (lane & 7) + (((lane >> 3) & 1) << 3);

    // =========================== F path state ==============================
    // smem: As2[2][32*FSTRIDE], Bs2[2][32*FSTRIDE] half2 (67584 B total)
    half2* As2 = (half2*)basep;
    half2* Bs2 = As2 + 2 * 32 * FSTRIDE;
    int tx = t & 15;
    int ty = (t >> 4) & 15;   // t/16 in 0..15

    for (;;) {
        __syncthreads();      // protects s_tile reuse across iterations
        if (t == 0) {
            unsigned old = atomicAdd(&g_ctr, isF ? 0x10000u : 1u);
            unsigned lo = old & 0xffffu, hi = old >> 16;
            s_tile = (lo + hi < (unsigned)NPAIRS)
                         ? (isF ? (NPAIRS - 1 - (int)hi) : (int)lo)
                         : -1;
        }
        __syncthreads();
        int tile = s_tile;
        if (tile < 0) break;

        int bi, bj;
        decode_tile(tile, bi, bj);
        const __half* __restrict__ gA = g_nrm + (size_t)bi * BM * D;
        const __half* __restrict__ gB = g_nrm + (size_t)bj * BM * D;
        const bool diag = (bi == bj);

        if (!isF) {
            // ================= HMMA tile (R5 pipeline) =================
            auto load_tile = [&](const __half* __restrict__ g, uint32_t s, int k0) {
                int row = t >> 1;
                const char* gp = (const char*)(g + (size_t)row * D + k0);
                uint32_t srow = s + (uint32_t)row * 128;
                #pragma unroll
                for (int i = 0; i < 4; i++) {
                    int c = (t & 1) * 4 + i;
                    cp16(srow + (((uint32_t)c ^ (row & 7)) << 4), gp + c * 16);
                }
            };

            uint32_t acc[4][4][2];
            #pragma unroll
            for (int mi = 0; mi < 4; mi++)
                #pragma unroll
                for (int nj = 0; nj < 4; nj++) { acc[mi][nj][0] = 0u; acc[mi][nj][1] = 0u; }

            load_tile(gA, sA[0], 0);
            load_tile(gB, sB[0], 0);
            cp_commit();
            load_tile(gA, sA[1], BK);
            load_tile(gB, sB[1], BK);
            cp_commit();

            for (int c = 0; c < NCHUNKS; c++) {
                if (c < NCHUNKS - 1) cp_wait<1>(); else cp_wait<0>();
                __syncthreads();

                if (c + 2 < NCHUNKS) {
                    load_tile(gA, sA[(c + 2) % NSTAGE], (c + 2) * BK);
                    load_tile(gB, sB[(c + 2) % NSTAGE], (c + 2) * BK);
                    cp_commit();
                }

                uint32_t a_base = sA[c % NSTAGE], b_base = sB[c % NSTAGE];
                #pragma unroll
                for (int kk = 0; kk < 4; kk++) {
                    uint32_t Af[4][4], Bf[2][4];
                    int kchunk = (kk * 16 + a_kq) >> 3;
                    #pragma unroll
                    for (int mi = 0; mi < 4; mi++) {
                        int r = a_row + mi * 16;
                        ldsm_x4(Af[mi], a_base + (uint32_t)r * 128 +
                                        (((uint32_t)kchunk ^ (r & 7)) << 4));
                    }
                    #pragma unroll
                    for (int p = 0; p < 2; p++) {
                        int r = b_row + p * 16;
                        ldsm_x4(Bf[p], b_base + (uint32_t)r * 128 +
                                       (((uint32_t)kchunk ^ (r & 7)) << 4));
                    }
                    #pragma unroll
                    for (int mi = 0; mi < 4; mi++)
                        #pragma unroll
                        for (int nj = 0; nj < 4; nj++)
                            mma16816_f16(acc[mi][nj], Af[mi],
                                         Bf[nj >> 1][nj & 1], Bf[nj >> 1][(nj & 1) + 2]);
                }
                __syncthreads();
            }

            int lrow0 = warp_m * 64 + (lane >> 2);
            int lcol0 = warp_n * 32 + (lane & 3) * 2;
            #pragma unroll
            for (int mi = 0; mi < 4; mi++)
                #pragma unroll
                for (int nj = 0; nj < 4; nj++) {
                    int rm = lrow0 + mi * 16;
                    int cn = lcol0 + nj * 8;
                    #pragma unroll
                    for (int r = 0; r < 2; r++) {
                        int im = rm + r * 8;
                        float2 f2 = __half22float2(*(__half2*)&acc[mi][nj][r]);
                        bool ok0 = diag ? (im < cn) : true;
                        bool ok1 = diag ? (im < cn + 1) : true;
                        if (ok0 && f2.x > 0.0f) local += f2.x;
                        if (ok1 && f2.y > 0.0f) local += f2.y;
                    }
                }
        } else {
            // ================= HFMA2 tile (fma pipe) =================
            // loader: thread t -> row r = t>>1, k2-half kb = (t&1)*16.
            auto f_load = [&](const __half* __restrict__ g, half2* s, int k0) {
                int r  = t >> 1;
                int kb = (t & 1) * 16;
                const uint4* src = (const uint4*)(g + (size_t)r * D + k0 + kb * 2);
                #pragma unroll
                for (int i = 0; i < 4; i++) {
                    uint4 v = src[i];
                    uint32_t* col = (uint32_t*)(s + (kb + i * 4) * FSTRIDE + r);
                    col[0 * FSTRIDE] = v.x;
                    col[1 * FSTRIDE] = v.y;
                    col[2 * FSTRIDE] = v.z;
                    col[3 * FSTRIDE] = v.w;
                }
            };

            half2 c2[8][8];
            #pragma unroll
            for (int i = 0; i < 8; i++)
                #pragma unroll
                for (int j = 0; j < 8; j++) c2[i][j] = __float2half2_rn(0.0f);

            f_load(gA, As2, 0);
            f_load(gB, Bs2, 0);
            __syncthreads();

            for (int c = 0; c < NCHUNKS; c++) {
                if (c + 1 < NCHUNKS) {
                    f_load(gA, As2 + ((c + 1) & 1) * 32 * FSTRIDE, (c + 1) * BK);
                    f_load(gB, Bs2 + ((c + 1) & 1) * 32 * FSTRIDE, (c + 1) * BK);
                }
                half2* Ab = As2 + (c & 1) * 32 * FSTRIDE;
                half2* Bb = Bs2 + (c & 1) * 32 * FSTRIDE;
                #pragma unroll 4
                for (int k2 = 0; k2 < 32; k2++) {
                    half2 a2[8], b2[8];
                    *(uint4*)&a2[0] = *(uint4*)(Ab + k2 * FSTRIDE + ty * 4);
                    *(uint4*)&a2[4] = *(uint4*)(Ab + k2 * FSTRIDE + 64 + ty * 4);
                    *(uint4*)&b2[0] = *(uint4*)(Bb + k2 * FSTRIDE + tx * 4);
                    *(uint4*)&b2[4] = *(uint4*)(Bb + k2 * FSTRIDE + 64 + tx * 4);
                    #pragma unroll
                    for (int i = 0; i < 8; i++)
                        #pragma unroll
                        for (int j = 0; j < 8; j++)
                            c2[i][j] = __hfma2(a2[i], b2[j], c2[i][j]);
                }
                __syncthreads();
            }

            #pragma unroll
            for (int i = 0; i < 8; i++) {
                int li = (i < 4) ? (ty * 4 + i) : (64 + ty * 4 + i - 4);
                #pragma unroll
                for (int j = 0; j < 8; j++) {
                    int lj = (j < 4) ? (tx * 4 + j) : (64 + tx * 4 + j - 4);
                    float v = __low2float(c2[i][j]) + __high2float(c2[i][j]);
                    bool ok = diag ? (li < lj) : true;
                    if (ok && v > 0.0f) local += v;
                }
            }
        }
    }

    // final reduction (once per CTA)
    #pragma unroll
    for (int o = 16; o; o >>= 1) local += __shfl_xor_sync(0xffffffffu, local, o);
    if (lane == 0) red[wid] = local;
    __syncthreads();
    if (t == 0) {
        float s = 0.0f;
        #pragma unroll
        for (int w = 0; w < 8; w++) s += red[w];
        atomicAdd(&g_accum, (double)s);
    }
}

// ---------------------------------------------------------------------------
// Kernel 3: finalize.
// ---------------------------------------------------------------------------
__global__ void finalize_kernel(float* __restrict__ out, int out_size) {
    double v = 2.0 * g_accum / ((double)N * (double)N);
    float f = (float)v;
    out[0] = f;
    if (out_size > 1) out[1] = f;
}

extern "C" void kernel_launch(void* const* d_in, const int* in_sizes, int n_in,
                              void* d_out, int out_size) {
    const float* id = (const float*)d_in[0];
    cudaFuncSetAttribute(gram_dual_kernel, cudaFuncAttributeMaxDynamicSharedMemorySize,
                         SMEM_BYTES);
    normalize_kernel<<<N / 8, 256>>>(id);
    gram_dual_kernel<<<2 * GRID_SMS, 256, SMEM_BYTES>>>();
    finalize_kernel<<<1, 1>>>((float*)d_out, out_size);
}

// round 8
// speedup vs baseline: 2.1374x; 1.5111x over previous
#include <cuda_runtime.h>
#include <cstdint>
#include <math.h>

#define N 8192
#define D 512
#define BM 128
#define NT (N / BM)                 // 64
#define NPAIRS (NT * (NT + 1) / 2)  // 2080
#define BK 128                      // fp8 K elements per chunk (128B rows)
#define NCHUNKS (D / BK)            // 4
#define NSTAGE 3
#define TILE_BYTES (BM * BK)        // 16384 (fp8)
#define SMEM_BYTES (1024 + 2 * NSTAGE * TILE_BYTES)

__device__ uint8_t g_q[N * D];      // e4m3-quantized unit rows
__device__ float   g_scale[N];      // per-row quant scale
__device__ double  g_accum;

// ---------------------------------------------------------------------------
// PTX helpers (arch-agnostic)
// ---------------------------------------------------------------------------
__device__ __forceinline__ uint32_t smem_u32(const void* p) {
    uint32_t a;
    asm("{ .reg .u64 t; cvta.to.shared.u64 t, %1; cvt.u32.u64 %0, t; }" : "=r"(a) : "l"(p));
    return a;
}
__device__ __forceinline__ void cp16(uint32_t saddr, const void* g) {
    asm volatile("cp.async.cg.shared.global [%0], [%1], 16;" :: "r"(saddr), "l"(g) : "memory");
}
__device__ __forceinline__ void cp_commit() {
    asm volatile("cp.async.commit_group;" ::: "memory");
}
template <int NN>
__device__ __forceinline__ void cp_wait() {
    asm volatile("cp.async.wait_group %0;" :: "n"(NN) : "memory");
}
__device__ __forceinline__ void ldsm_x4(uint32_t* r, uint32_t addr) {
    asm volatile("ldmatrix.sync.aligned.m8n8.x4.shared.b16 {%0,%1,%2,%3}, [%4];"
                 : "=r"(r[0]), "=r"(r[1]), "=r"(r[2]), "=r"(r[3]) : "r"(addr));
}

// fp8 e4m3 QMMA, k=32 per instruction, f32 accumulate (sm_89-era legacy mma).
__device__ __forceinline__ void qmma16832(float* d, const uint32_t* a,
                                          uint32_t b0, uint32_t b1) {
    asm volatile(
        "mma.sync.aligned.m16n8k32.row.col.f32.e4m3.e4m3.f32 "
        "{%0,%1,%2,%3}, {%4,%5,%6,%7}, {%8,%9}, {%0,%1,%2,%3};"
        : "+f"(d[0]), "+f"(d[1]), "+f"(d[2]), "+f"(d[3])
        : "r"(a[0]), "r"(a[1]), "r"(a[2]), "r"(a[3]), "r"(b0), "r"(b1));
}

// pack two floats -> e4m3x2 (16 bits), a in upper byte, b in lower byte
__device__ __forceinline__ uint32_t cvt_e4m3x2(float hi, float lo) {
    uint16_t h;
    asm("cvt.rn.satfinite.e4m3x2.f32 %0, %1, %2;" : "=h"(h) : "f"(hi), "f"(lo));
    return (uint32_t)h;
}

// ---------------------------------------------------------------------------
// Kernel 1: row L2-normalize + per-row e4m3 quantization. One WARP per row.
// ---------------------------------------------------------------------------
__global__ __launch_bounds__(256) void quantize_kernel(const float* __restrict__ in) {
    int row  = blockIdx.x * 8 + (threadIdx.x >> 5);
    int lane = threadIdx.x & 31;
    if (blockIdx.x == 0 && threadIdx.x == 0) g_accum = 0.0;

    const float4* src = (const float4*)(in + (size_t)row * D);
    float4 v[4];
    float ss = 0.0f;
    #pragma unroll
    for (int i = 0; i < 4; i++) {
        v[i] = src[i * 32 + lane];
        ss += v[i].x * v[i].x + v[i].y * v[i].y + v[i].z * v[i].z + v[i].w * v[i].w;
    }
    #pragma unroll
    for (int o = 16; o; o >>= 1) ss += __shfl_xor_sync(0xffffffffu, ss, o);
    float inv = rsqrtf(ss);

    float amax = 0.0f;
    #pragma unroll
    for (int i = 0; i < 4; i++) {
        amax = fmaxf(amax, fmaxf(fmaxf(fabsf(v[i].x), fabsf(v[i].y)),
                                 fmaxf(fabsf(v[i].z), fabsf(v[i].w))));
    }
    amax *= inv;
    #pragma unroll
    for (int o = 16; o; o >>= 1) amax = fmaxf(amax, __shfl_xor_sync(0xffffffffu, amax, o));

    float s    = amax * (1.0f / 448.0f);
    float qmul = inv * (448.0f / amax);     // y -> q grid
    if (lane == 0) g_scale[row] = s;

    uint32_t* dst = (uint32_t*)(g_q + (size_t)row * D);
    #pragma unroll
    for (int i = 0; i < 4; i++) {
        uint32_t lo16 = cvt_e4m3x2(v[i].y * qmul, v[i].x * qmul);  // e1<<8 | e0
        uint32_t hi16 = cvt_e4m3x2(v[i].w * qmul, v[i].z * qmul);  // e3<<8 | e2
        dst[i * 32 + lane] = lo16 | (hi16 << 16);
    }
}

// ---------------------------------------------------------------------------
// Kernel 2: upper-triangle 128x128 Gram tiles via QMMA e4m3 (k32).
// 256 threads = 8 warps (2 x 4), warp tile 64x32.
// 3-stage cp.async pipeline, one __syncthreads per 128-deep K-chunk.
// SMEM tiles [128 rows][128 fp8], 128B rows, XOR-swizzled 16B chunks.
// (fragment/addressing layout identical to the verified R6 int8-k32 kernel)
// ---------------------------------------------------------------------------
extern __shared__ char dynsmem[];

__global__ __launch_bounds__(256, 2) void gram_qmma_kernel() {
    int b = blockIdx.x;
    int bj = (int)((sqrtf(8.0f * (float)b + 1.0f) - 1.0f) * 0.5f);
    while ((bj + 1) * (bj + 2) / 2 <= b) bj++;
    while (bj * (bj + 1) / 2 > b) bj--;
    int bi = b - bj * (bj + 1) / 2;

    const uint8_t* __restrict__ gA = g_q + (size_t)bi * BM * D;
    const uint8_t* __restrict__ gB = g_q + (size_t)bj * BM * D;
    const bool diag = (bi == bj);

    int t      = threadIdx.x;
    int wid    = t >> 5;
    int lane   = t & 31;
    int warp_m = wid & 1;    // 2 warps over M (64 each)
    int warp_n = wid >> 1;   // 4 warps over N (32 each)

    __shared__ float sScale[256];   // [0..127]=A-row scales, [128..255]=B-row scales
    if (t < 128) sScale[t] = g_scale[bi * BM + t];
    else         sScale[t] = g_scale[bj * BM + (t - 128)];

    uint32_t smem0 = smem_u32(dynsmem);
    uint32_t base  = (smem0 + 1023) & ~1023u;
    uint32_t sA[NSTAGE], sB[NSTAGE];
    #pragma unroll
    for (int s = 0; s < NSTAGE; s++) {
        sA[s] = base + (2 * s)     * TILE_BYTES;
        sB[s] = base + (2 * s + 1) * TILE_BYTES;
    }

    // --- async tile loader: 128 rows x 128 fp8 (= 8 x 16B chunks/row) ---
    auto load_tile = [&](const uint8_t* __restrict__ g, uint32_t s, int k0) {
        int row = t >> 1;
        const char* gp = (const char*)(g + (size_t)row * D + k0);
        uint32_t srow = s + (uint32_t)row * 128;
        #pragma unroll
        for (int i = 0; i < 4; i++) {
            int c = (t & 1) * 4 + i;
            cp16(srow + (((uint32_t)c ^ (row & 7)) << 4), gp + c * 16);
        }
    };

    float acc[4][4][4];
    #pragma unroll
    for (int mi = 0; mi < 4; mi++)
        #pragma unroll
        for (int nj = 0; nj < 4; nj++)
            #pragma unroll
            for (int r = 0; r < 4; r++) acc[mi][nj][r] = 0.0f;

    // prologue: stages 0 and 1 in flight
    load_tile(gA, sA[0], 0);
    load_tile(gB, sB[0], 0);
    cp_commit();
    load_tile(gA, sA[1], BK);
    load_tile(gB, sB[1], BK);
    cp_commit();

    // ldmatrix lane addressing (b16 view; k32 step = 2 x 16B chunks)
    int a_row = warp_m * 64 + (lane & 15);                            // + mi*16
    int a_kh  = lane >> 4;                                            // 16B half select
    int b_row = warp_n * 32 + (lane & 7) + (((lane >> 3) & 1) << 3);  // + p*16

    for (int c = 0; c < NCHUNKS; c++) {
        if (c < NCHUNKS - 1) cp_wait<1>(); else cp_wait<0>();
        __syncthreads();

        if (c + 2 < NCHUNKS) {
            load_tile(gA, sA[(c + 2) % NSTAGE], (c + 2) * BK);
            load_tile(gB, sB[(c + 2) % NSTAGE], (c + 2) * BK);
            cp_commit();
        }

        uint32_t a_base = sA[c % NSTAGE], b_base = sB[c % NSTAGE];
        #pragma unroll
        for (int kk = 0; kk < 4; kk++) {          // 4 k32-steps per 128-chunk
            uint32_t Af[4][4], Bf[2][4];
            int kchunk = kk * 2 + a_kh;           // 16B-chunk index in row (0..7)
            #pragma unroll
            for (int mi = 0; mi < 4; mi++) {
                int r = a_row + mi * 16;
                ldsm_x4(Af[mi], a_base + (uint32_t)r * 128 +
                                (((uint32_t)kchunk ^ (r & 7)) << 4));
            }
            #pragma unroll
            for (int p = 0; p < 2; p++) {
                int r = b_row + p * 16;
                ldsm_x4(Bf[p], b_base + (uint32_t)r * 128 +
                               (((uint32_t)kchunk ^ (r & 7)) << 4));
            }
            #pragma unroll
            for (int mi = 0; mi < 4; mi++)
                #pragma unroll
                for (int nj = 0; nj < 4; nj++)
                    qmma16832(acc[mi][nj], Af[mi],
                              Bf[nj >> 1][nj & 1], Bf[nj >> 1][(nj & 1) + 2]);
        }
    }

    // Epilogue: scale (s_i * s_j), relu, strict-upper mask on diagonal tiles.
    int lrow0 = warp_m * 64 + (lane >> 2);
    int lcol0 = warp_n * 32 + (lane & 3) * 2;

    float si[4][2], sj[4][2];
    #pragma unroll
    for (int mi = 0; mi < 4; mi++)
        #pragma unroll
        for (int h = 0; h < 2; h++)
            si[mi][h] = sScale[lrow0 + mi * 16 + h * 8];
    #pragma unroll
    for (int nj = 0; nj < 4; nj++)
        #pragma unroll
        for (int bcol = 0; bcol < 2; bcol++)
            sj[nj][bcol] = sScale[128 + lcol0 + nj * 8 + bcol];

    float local = 0.0f;
    #pragma unroll
    for (int mi = 0; mi < 4; mi++) {
        #pragma unroll
        for (int nj = 0; nj < 4; nj++) {
            #pragma unroll
            for (int r = 0; r < 4; r++) {
                int h  = r >> 1;
                int bc = r & 1;
                int im = lrow0 + mi * 16 + h * 8;
                int jn = lcol0 + nj * 8 + bc;
                float d = acc[mi][nj][r];
                bool ok = diag ? (im < jn) : true;
                if (ok && d > 0.0f) local += d * si[mi][h] * sj[nj][bc];
            }
        }
    }

    #pragma unroll
    for (int o = 16; o; o >>= 1) local += __shfl_xor_sync(0xffffffffu, local, o);
    __shared__ float red[8];
    if (lane == 0) red[wid] = local;
    __syncthreads();
    if (t == 0) {
        float s = 0.0f;
        #pragma unroll
        for (int w = 0; w < 8; w++) s += red[w];
        atomicAdd(&g_accum, (double)s);
    }
}

// ---------------------------------------------------------------------------
// Kernel 3: finalize. Off-diagonal symmetric sum doubled, mean over N*N.
// ---------------------------------------------------------------------------
__global__ void finalize_kernel(float* __restrict__ out, int out_size) {
    double v = 2.0 * g_accum / ((double)N * (double)N);
    float f = (float)v;
    out[0] = f;
    if (out_size > 1) out[1] = f;
}

extern "C" void kernel_launch(void* const* d_in, const int* in_sizes, int n_in,
                              void* d_out, int out_size) {
    const float* id = (const float*)d_in[0];
    cudaFuncSetAttribute(gram_qmma_kernel, cudaFuncAttributeMaxDynamicSharedMemorySize,
                         SMEM_BYTES);
    quantize_kernel<<<N / 8, 256>>>(id);
    gram_qmma_kernel<<<NPAIRS, 256, SMEM_BYTES>>>();
    finalize_kernel<<<1, 1>>>((float*)d_out, out_size);
}